// round 17
// baseline (speedup 1.0000x reference)
#include <cuda_runtime.h>
#include <cuda_bf16.h>
#include <cstdint>

typedef unsigned int u32;

#define NB 512
#define NT 512
#define NC 64
#define HALF_T 256        // fw owns t in [0,256); bw owns [256,512)
#define BPC 2             // batches per CTA
#define THREADS 256       // 4 teams x 64 threads; team = one (batch, direction)
#define FULLMASK 0xffffffffu
#define LN2F 0.6931471805599453f

__device__ float    g_partial[NB];
__device__ unsigned g_done;

static __device__ __forceinline__ __nv_bfloat162 u2b(u32 u) {
    __nv_bfloat162 r; *reinterpret_cast<u32*>(&r) = u; return r;
}

// One named barrier per 64-thread team (ids 1..4; id 0 = __syncthreads).
#define TEAM_BAR() asm volatile("bar.sync %0, 64;" :: "r"(team + 1) : "memory")

// 64-wide GEMV, one output column per thread: 8x broadcast LDS.128 feed
// 32 HFMA2 (pair-packed); both halves of each acc are partials of column c.
#define GEMV64T(IN, QC) do {                                                     \
    const uint4* pb_ = (const uint4*)(IN);                                       \
    __nv_bfloat162 a0_ = u2b(0u), a1_ = u2b(0u), a2_ = u2b(0u), a3_ = u2b(0u);   \
    _Pragma("unroll")                                                            \
    for (int k_ = 0; k_ < 8; k_++) {                                             \
        uint4 w_ = pb_[k_];                                                      \
        a0_ = __hfma2(u2b(w_.x), e2[4 * k_ + 0], a0_);                           \
        a1_ = __hfma2(u2b(w_.y), e2[4 * k_ + 1], a1_);                           \
        a2_ = __hfma2(u2b(w_.z), e2[4 * k_ + 2], a2_);                           \
        a3_ = __hfma2(u2b(w_.w), e2[4 * k_ + 3], a3_);                           \
    }                                                                            \
    float2 f_ = __bfloat1622float2(                                              \
        __hadd2(__hadd2(a0_, a1_), __hadd2(a2_, a3_)));                          \
    QC = f_.x + f_.y;                                                            \
} while (0)

// Deferred exact power-of-2 renorm: REDUX stores each warp's bf16-bit max at
// group END; APPLY (next group START) combines the two maxes -> uniform scale.
// bf16 bits of positive values are int-monotonic. Scale 2^(127-e) is exact.
#define APPLY_SCALE(REG) do {                                                    \
    u32 mA_ = tmax[team][0], mB_ = tmax[team][1];                                \
    u32 mm_ = mA_ > mB_ ? mA_ : mB_;                                             \
    int e_ = (int)((mm_ >> 7) & 0xFF);                                           \
    (REG) *= __int_as_float((254 - e_) << 23);                                   \
    logZ += (float)(e_ - 127) * LN2F;                                            \
} while (0)

#define DO_REDUX(PB) do {                                                        \
    u32 wm_ = (u32)__reduce_max_sync(FULLMASK,                                   \
                  (int)(u32)__bfloat16_as_ushort(PB));                           \
    if ((wtid & 31) == 0) tmax[team][wtid >> 5] = wm_;                           \
} while (0)

// Forward step: q_c = sum_i p_i E[i][c]; masked: p = q * exp(emit_t).
#define STEP_F(IN, OUT, EMV, M, APPLY, REDUX) do {                               \
    float ex_ = __expf(EMV);                                                     \
    float qc_; GEMV64T(IN, qc_);                                                 \
    if (M) px = qc_ * ex_;                                                       \
    if (APPLY) APPLY_SCALE(px);                                                  \
    __nv_bfloat16 pb_ = __float2bfloat16(px);                                    \
    if (REDUX) DO_REDUX(pb_);                                                    \
    *(__nv_bfloat16*)((char*)(OUT) + 2 * c) = pb_;                               \
    TEAM_BAR();                                                                  \
} while (0)

// Backward step: q_c = sum_k E[c][k] v_k; masked: beta = q;
// store v' = beta * exp(emit_{u-1}).
#define STEP_B(IN, OUT, EMV, M, APPLY, REDUX) do {                               \
    float ex_ = __expf(EMV);                                                     \
    float qc_; GEMV64T(IN, qc_);                                                 \
    if (M) pbeta = qc_;                                                          \
    if (APPLY) APPLY_SCALE(pbeta);                                               \
    __nv_bfloat16 pb_ = __float2bfloat16(pbeta * ex_);                           \
    if (REDUX) DO_REDUX(pb_);                                                    \
    *(__nv_bfloat16*)((char*)(OUT) + 2 * c) = pb_;                               \
    TEAM_BAR();                                                                  \
} while (0)

__global__ void __launch_bounds__(THREADS, 2) crf_forward(
    const float* __restrict__ emissions,   // [B, T, C]
    const int*   __restrict__ tags,        // [B, T]
    const int*   __restrict__ mask,        // [B, T]
    const float* __restrict__ trans,       // [C, C]
    const float* __restrict__ startt,      // [C]
    const float* __restrict__ endt,        // [C]
    float*       __restrict__ out)         // [1]
{
    // Per-team double-buffered packed bf16 state (entry k = (v_2k, v_2k+1)).
    __shared__ __align__(16) u32   sbuf[4][2][32];
    __shared__ __align__(8)  u32   tmax[4][2];
    __shared__ float bbuf[BPC][NC];          // beta_256 (f32)
    __shared__ float s_logZb[BPC], s_numb[BPC];
    __shared__ float s_part[BPC][2];
    __shared__ bool  s_last;

    const int tid  = threadIdx.x;
    const int team = tid >> 6;               // 0..3
    const int wtid = tid & 63;               // 0..63
    const int c    = wtid;                   // owned state/column
    const int bl   = team >> 1;              // batch within CTA
    const int role = team & 1;               // 0 = forward, 1 = backward
    const int b    = blockIdx.x * BPC + bl;

    u32* const A = sbuf[team][0];
    u32* const B = sbuf[team][1];

    const float* em = emissions + (size_t)b * NT * NC;
    const int*   tg = tags + (size_t)b * NT;
    const int*   mk = mask + (size_t)b * NT;

    __nv_bfloat162 e2[32];
    float logZ = 0.f;

    if (role == 0) {
        // ========================= FORWARD (t = 0..255) =========================
        float px;
        // e2[k] = (exp T[2k][c], exp T[2k+1][c])
#pragma unroll
        for (int k = 0; k < 32; k++) {
            float t0v = trans[(2 * k) * NC + c];
            float t1v = trans[(2 * k + 1) * NC + c];
            e2[k] = __floats2bfloat162_rn(__expf(t0v), __expf(t1v));
        }

        // numerator (f32), first half (warp 0 of team only)
        float num = 0.f;
        if (wtid < 32) {
#pragma unroll 2
            for (int t = wtid; t < HALF_T; t += 32) {
                int tt = tg[t];
                if (t > 0 && mk[t])
                    num += trans[tg[t - 1] * NC + tt] + em[(size_t)t * NC + tt];
            }
#pragma unroll
            for (int o = 16; o > 0; o >>= 1)
                num += __shfl_down_sync(FULLMASK, num, o);
            if (wtid == 0) {
                int t0 = tg[0];
                num += startt[t0] + em[t0];
            }
        }

        // prologue loads
        float eP1 = em[(size_t)1 * NC + c];
        float eP2 = em[(size_t)2 * NC + c];
        float eP3 = em[(size_t)3 * NC + c];
        int4  mk03 = *(const int4*)(mk);
        int4  mc   = *(const int4*)(mk + 4);
        float ec0 = em[(size_t)4 * NC + c];
        float ec1 = em[(size_t)5 * NC + c];
        float ec2 = em[(size_t)6 * NC + c];
        float ec3 = em[(size_t)7 * NC + c];

        // init t = 0: |start+em| <= ~10 -> exp safe in f32/bf16, no max needed
        px = __expf(startt[c] + em[c]);
        *(__nv_bfloat16*)((char*)A + 2 * c) = __float2bfloat16(px);
        TEAM_BAR();

        STEP_F(A, B, eP1, mk03.y, false, false);
        STEP_F(B, A, eP2, mk03.z, false, false);
        STEP_F(A, B, eP3, mk03.w, false, true);   // publish max

#pragma unroll 1
        for (int t0 = 4; t0 < HALF_T; t0 += 4) {
            float en0 = ec0, en1 = ec1, en2 = ec2, en3 = ec3;
            int4  mn  = mc;
            if (t0 + 4 < HALF_T) {
                const float* p4 = em + (size_t)(t0 + 4) * NC + c;
                en0 = p4[0];  en1 = p4[NC];
                en2 = p4[2 * NC];  en3 = p4[3 * NC];
                mn  = *(const int4*)(mk + t0 + 4);
            }
            STEP_F(B, A, ec0, mc.x, true,  false);  // apply last group's scale
            STEP_F(A, B, ec1, mc.y, false, false);
            STEP_F(B, A, ec2, mc.z, false, false);
            STEP_F(A, B, ec3, mc.w, false, true);   // publish max
            ec0 = en0; ec1 = en1; ec2 = en2; ec3 = en3; mc = mn;
        }

        __syncthreads();   // bbuf, s_logZb, s_numb published by bw team

        float contrib = px * bbuf[bl][c];
#pragma unroll
        for (int o = 16; o > 0; o >>= 1)
            contrib += __shfl_down_sync(FULLMASK, contrib, o);
        if ((wtid & 31) == 0) s_part[bl][wtid >> 5] = contrib;
        __syncthreads();
        if (wtid == 0)
            g_partial[b] = logZ + s_logZb[bl]
                           + __logf(s_part[bl][0] + s_part[bl][1])
                           - (num + s_numb[bl]);
    } else {
        // ========================= BACKWARD (t = 511..256) ======================
        float pbeta;
        // e2[k] = (exp T[c][2k], exp T[c][2k+1])
#pragma unroll
        for (int k = 0; k < 32; k++) {
            float2 rv = *(const float2*)(trans + c * NC + 2 * k);
            e2[k] = __floats2bfloat162_rn(__expf(rv.x), __expf(rv.y));
        }

        // numerator (f32), second half + end term (warp 0 of team only)
        if (wtid < 32) {
            float num = 0.f;
            int   cnt = 0;
#pragma unroll 2
            for (int t = wtid; t < NT; t += 32) {
                int m = mk[t];
                cnt += m;
                if (t >= HALF_T && m) {
                    int tt = tg[t];
                    num += trans[tg[t - 1] * NC + tt] + em[(size_t)t * NC + tt];
                }
            }
            cnt = __reduce_add_sync(FULLMASK, cnt);
#pragma unroll
            for (int o = 16; o > 0; o >>= 1)
                num += __shfl_down_sync(FULLMASK, num, o);
            if (wtid == 0)
                s_numb[bl] = num + endt[tg[cnt - 1]];
        }

        // prologue loads
        float eP0 = em[(size_t)510 * NC + c];
        float eP1 = em[(size_t)509 * NC + c];
        float eP2 = em[(size_t)508 * NC + c];
        int mk511 = mk[511], mk510 = mk[510], mk509 = mk[509];
        float be0 = em[(size_t)507 * NC + c];
        float be1 = em[(size_t)506 * NC + c];
        float be2 = em[(size_t)505 * NC + c];
        float be3 = em[(size_t)504 * NC + c];
        int m0g = mk[508], m1g = mk[507], m2g = mk[506], m3g = mk[505];
        int mk256 = mk[256];
        float emI = em[(size_t)511 * NC + c];

        // init: beta_511 = exp(end); store v_511 = beta * exp(e_511)
        pbeta = __expf(endt[c]);
        *(__nv_bfloat16*)((char*)A + 2 * c) =
            __float2bfloat16(pbeta * __expf(emI));
        TEAM_BAR();

        STEP_B(A, B, eP0, mk511, false, false);
        STEP_B(B, A, eP1, mk510, false, false);
        STEP_B(A, B, eP2, mk509, false, true);   // publish max

#pragma unroll 1
        for (int u0 = 508; u0 >= 260; u0 -= 4) {
            float bn0 = be0, bn1 = be1, bn2 = be2, bn3 = be3;
            int n0 = m0g, n1 = m1g, n2 = m2g, n3 = m3g;
            if (u0 > 260) {
                const int u1 = u0 - 4;
                const float* p4 = em + (size_t)(u1 - 4) * NC + c;
                bn0 = p4[3 * NC];   // e_{u1-1}
                bn1 = p4[2 * NC];   // e_{u1-2}
                bn2 = p4[NC];       // e_{u1-3}
                bn3 = p4[0];        // e_{u1-4}
                n0 = mk[u1]; n1 = mk[u1 - 1]; n2 = mk[u1 - 2]; n3 = mk[u1 - 3];
            }
            STEP_B(B, A, be0, m0g, true,  false);
            STEP_B(A, B, be1, m1g, false, false);
            STEP_B(B, A, be2, m2g, false, false);
            STEP_B(A, B, be3, m3g, false, true);
            be0 = bn0; be1 = bn1; be2 = bn2; be3 = bn3;
            m0g = n0; m1g = n1; m2g = n2; m3g = n3;
        }

        // final step u = 256: select only (no emission, no store, no bar)
        {
            float qc_;
            GEMV64T(B, qc_);
            if (mk256) pbeta = qc_;
        }
        bbuf[bl][c] = pbeta;
        if (wtid == 0) s_logZb[bl] = logZ;

        __syncthreads();   // matches fw team's barrier
        __syncthreads();
    }

    // ---- fused final reduction: last CTA to finish reduces all 512 ----
    __syncthreads();
    if (tid == 0) {
        __threadfence();
        unsigned prev = atomicAdd(&g_done, 1u);
        s_last = (prev == gridDim.x - 1);
    }
    __syncthreads();
    if (s_last && tid < 32) {
        __threadfence();
        float s = 0.f;
        const float4* gp = (const float4*)g_partial;
#pragma unroll
        for (int k = 0; k < 4; k++) {
            float4 v = __ldcg(gp + tid + 32 * k);
            s += (v.x + v.y) + (v.z + v.w);
        }
#pragma unroll
        for (int o = 16; o > 0; o >>= 1)
            s += __shfl_down_sync(FULLMASK, s, o);
        if (tid == 0) {
            out[0] = s * (1.0f / (float)NB);
            g_done = 0;   // reset for next graph replay (deterministic)
        }
    }
}

extern "C" void kernel_launch(void* const* d_in, const int* in_sizes, int n_in,
                              void* d_out, int out_size) {
    const float* emissions = (const float*)d_in[0];
    const int*   tags      = (const int*)d_in[1];
    const int*   mask      = (const int*)d_in[2];
    const float* trans     = (const float*)d_in[3];
    const float* startt    = (const float*)d_in[4];
    const float* endt      = (const float*)d_in[5];
    (void)in_sizes; (void)n_in; (void)out_size;

    crf_forward<<<NB / BPC, THREADS>>>(emissions, tags, mask, trans, startt,
                                       endt, (float*)d_out);
}